// round 1
// baseline (speedup 1.0000x reference)
#include <cuda_runtime.h>
#include <math.h>

#define NTOK    131072
#define KEXP    16
#define IN_DIM  256
#define OUT_DIM 128
#define TILE_M  128
// sum over experts of ceil(cnt/128) <= floor(N/128) + (K-1) = 1024 + 15
#define MAX_TILES (NTOK / TILE_M + KEXP - 1)

// ---------------- device scratch (no allocation allowed) ----------------
__device__ int g_counts[KEXP];
__device__ int g_offsets[KEXP];
__device__ int g_cursor[KEXP];
__device__ int g_perm[NTOK];
__device__ int g_tile_expert[MAX_TILES];
__device__ int g_tile_start[MAX_TILES];
__device__ int g_tile_len[MAX_TILES];
__device__ int g_num_tiles;

// ---------------- 1. zero counters (graph replays must reset) ----------------
__global__ void zero_kernel() {
    int tid = threadIdx.x;
    if (tid < KEXP) g_counts[tid] = 0;
}

// ---------------- 2. per-expert histogram (block-aggregated atomics) ----------------
__global__ void hist_kernel(const int* __restrict__ z) {
    __shared__ int sh[KEXP];
    int tid = threadIdx.x;
    if (tid < KEXP) sh[tid] = 0;
    __syncthreads();
    int i = blockIdx.x * blockDim.x + tid;   // grid covers N exactly
    atomicAdd(&sh[z[i]], 1);
    __syncthreads();
    if (tid < KEXP) atomicAdd(&g_counts[tid], sh[tid]);
}

// ---------------- 3. exclusive scan + tile table build ----------------
__global__ void scan_kernel() {
    __shared__ int s_off[KEXP + 1];
    __shared__ int s_tp[KEXP + 1];
    int tid = threadIdx.x;
    if (tid == 0) {
        int off = 0, tp = 0;
        for (int e = 0; e < KEXP; e++) {
            s_off[e] = off;
            s_tp[e]  = tp;
            g_offsets[e] = off;
            g_cursor[e]  = off;
            int c = g_counts[e];
            off += c;
            tp  += (c + TILE_M - 1) / TILE_M;
        }
        s_off[KEXP] = off;
        s_tp[KEXP]  = tp;
        g_num_tiles = tp;
    }
    __syncthreads();
    int total = s_tp[KEXP];
    for (int idx = tid; idx < total; idx += blockDim.x) {
        int e = 0;
        while (s_tp[e + 1] <= idx) e++;
        int t = idx - s_tp[e];
        g_tile_expert[idx] = e;
        g_tile_start[idx]  = s_off[e] + t * TILE_M;
        int rem = g_counts[e] - t * TILE_M;
        g_tile_len[idx] = rem < TILE_M ? rem : TILE_M;
    }
}

// ---------------- 4. scatter token ids into per-expert contiguous ranges ----------------
__global__ void scatter_kernel(const int* __restrict__ z) {
    __shared__ int sh_cnt[KEXP];
    __shared__ int sh_base[KEXP];
    int tid = threadIdx.x;
    if (tid < KEXP) sh_cnt[tid] = 0;
    __syncthreads();
    int i = blockIdx.x * blockDim.x + tid;
    int e = z[i];
    int lr = atomicAdd(&sh_cnt[e], 1);
    __syncthreads();
    if (tid < KEXP) {
        int c = sh_cnt[tid];
        sh_base[tid] = (c > 0) ? atomicAdd(&g_cursor[tid], c) : 0;
    }
    __syncthreads();
    g_perm[sh_base[e] + lr] = i;
}

// ---------------- 5. fused expert MLP: (x@W1+b1).relu() @ W2 + b2 -> softmax ----------------
// CTA: one (expert, 128-token) tile. 256 threads as 16x16; each thread owns an
// 8-token x 8-out register tile. K staged through SMEM in chunks of 32.
__global__ __launch_bounds__(256, 2) void mlp_kernel(
    const float* __restrict__ x,
    const float* __restrict__ W1,
    const float* __restrict__ b1,
    const float* __restrict__ W2,
    const float* __restrict__ b2,
    float* __restrict__ out)
{
    int bid = blockIdx.x;
    if (bid >= g_num_tiles) return;
    int e     = g_tile_expert[bid];
    int start = g_tile_start[bid];
    int len   = g_tile_len[bid];

    __shared__ float xs[32][TILE_M + 4];   // transposed x chunk: xs[k][m]
    __shared__ float ws[32][OUT_DIM];      // W1 chunk: ws[k][n]
    __shared__ int   tok[TILE_M];

    int tid = threadIdx.x;
    if (tid < TILE_M) tok[tid] = (tid < len) ? g_perm[start + tid] : -1;
    __syncthreads();

    const float* W1e = W1 + (size_t)e * IN_DIM * OUT_DIM;

    float acc[8][8];
#pragma unroll
    for (int t = 0; t < 8; t++)
#pragma unroll
        for (int j = 0; j < 8; j++) acc[t][j] = 0.f;

    int tr = tid >> 4;      // 0..15 -> token group (8 tokens)
    int tc = tid & 15;      // 0..15 -> out group (8 outs)

    for (int k0 = 0; k0 < IN_DIM; k0 += 32) {
        // stage x chunk (gathered rows), transposed into xs[k][m]
#pragma unroll
        for (int i = 0; i < 4; i++) {
            int idx = i * 256 + tid;
            int m  = idx & (TILE_M - 1);
            int kq = idx >> 7;              // 0..7 -> 4 k values each
            int t  = tok[m];
            float4 v = make_float4(0.f, 0.f, 0.f, 0.f);
            if (t >= 0)
                v = *(const float4*)(x + (size_t)t * IN_DIM + k0 + kq * 4);
            xs[kq * 4 + 0][m] = v.x;
            xs[kq * 4 + 1][m] = v.y;
            xs[kq * 4 + 2][m] = v.z;
            xs[kq * 4 + 3][m] = v.w;
        }
        // stage W1 chunk
#pragma unroll
        for (int i = 0; i < 4; i++) {
            int idx = i * 256 + tid;
            int k  = idx >> 5;              // 0..31
            int nq = idx & 31;              // 0..31 float4s
            *(float4*)&ws[k][nq * 4] =
                *(const float4*)(W1e + (size_t)(k0 + k) * OUT_DIM + nq * 4);
        }
        __syncthreads();

#pragma unroll 2
        for (int kk = 0; kk < 32; kk++) {
            float a[8], b[8];
            *(float4*)&a[0] = *(const float4*)&xs[kk][tr * 8];
            *(float4*)&a[4] = *(const float4*)&xs[kk][tr * 8 + 4];
            *(float4*)&b[0] = *(const float4*)&ws[kk][tc * 8];
            *(float4*)&b[4] = *(const float4*)&ws[kk][tc * 8 + 4];
#pragma unroll
            for (int t = 0; t < 8; t++)
#pragma unroll
                for (int j = 0; j < 8; j++)
                    acc[t][j] = fmaf(a[t], b[j], acc[t][j]);
        }
        __syncthreads();
    }

    // epilogue: bias + ReLU + second layer partials (per-thread over its 8 outs)
    const float* b1e = b1 + (size_t)e * OUT_DIM + tc * 8;
    const float* w2e = W2 + (size_t)e * OUT_DIM * 2 + tc * 8 * 2;

    float p0[8], p1[8];
#pragma unroll
    for (int t = 0; t < 8; t++) { p0[t] = 0.f; p1[t] = 0.f; }

#pragma unroll
    for (int j = 0; j < 8; j++) {
        float bj  = b1e[j];
        float w20 = w2e[j * 2 + 0];
        float w21 = w2e[j * 2 + 1];
#pragma unroll
        for (int t = 0; t < 8; t++) {
            float h = fmaxf(acc[t][j] + bj, 0.f);
            p0[t] = fmaf(h, w20, p0[t]);
            p1[t] = fmaf(h, w21, p1[t]);
        }
    }

    // reduce across the 16 threads (tc lanes) sharing each token group.
    // tid = tr*16 + tc, so the 16 partners are a contiguous half-warp:
    // butterfly xor over d = 8,4,2,1 stays inside the group.
#pragma unroll
    for (int t = 0; t < 8; t++) {
        p0[t] += __shfl_xor_sync(0xFFFFFFFFu, p0[t], 8);
        p1[t] += __shfl_xor_sync(0xFFFFFFFFu, p1[t], 8);
        p0[t] += __shfl_xor_sync(0xFFFFFFFFu, p0[t], 4);
        p1[t] += __shfl_xor_sync(0xFFFFFFFFu, p1[t], 4);
        p0[t] += __shfl_xor_sync(0xFFFFFFFFu, p0[t], 2);
        p1[t] += __shfl_xor_sync(0xFFFFFFFFu, p1[t], 2);
        p0[t] += __shfl_xor_sync(0xFFFFFFFFu, p0[t], 1);
        p1[t] += __shfl_xor_sync(0xFFFFFFFFu, p1[t], 1);
    }

    // lane tc == t writes token m = tr*8 + t
    float l0 = 0.f, l1 = 0.f;
#pragma unroll
    for (int t = 0; t < 8; t++)
        if (tc == t) { l0 = p0[t]; l1 = p1[t]; }

    if (tc < 8) {
        int m = tr * 8 + tc;
        if (m < len) {
            l0 += b2[e * 2 + 0];
            l1 += b2[e * 2 + 1];
            float mx = fmaxf(l0, l1);
            float e0 = expf(l0 - mx);
            float e1 = expf(l1 - mx);
            float inv = 1.f / (e0 + e1);
            ((float2*)out)[tok[m]] = make_float2(e0 * inv, e1 * inv);
        }
    }
}

// ---------------- launch ----------------
extern "C" void kernel_launch(void* const* d_in, const int* in_sizes, int n_in,
                              void* d_out, int out_size) {
    const float* x  = (const float*)d_in[0];
    const int*   z  = (const int*)d_in[1];
    const float* W1 = (const float*)d_in[2];
    const float* b1 = (const float*)d_in[3];
    const float* W2 = (const float*)d_in[4];
    const float* b2 = (const float*)d_in[5];
    float* out = (float*)d_out;

    zero_kernel<<<1, 32>>>();
    hist_kernel<<<NTOK / 256, 256>>>(z);
    scan_kernel<<<1, 256>>>();
    scatter_kernel<<<NTOK / 256, 256>>>(z);
    mlp_kernel<<<MAX_TILES, 256>>>(x, W1, b1, W2, b2, out);
}

// round 3
// speedup vs baseline: 3.5496x; 3.5496x over previous
#include <cuda_runtime.h>
#include <cstdint>
#include <math.h>

#define NTOK    131072
#define KEXP    16
#define IN_DIM  256
#define OUT_DIM 128
#define TILE_M  128
#define MAX_TILES (NTOK / TILE_M + KEXP - 1)

#define KC      32                 // k-chunk
#define NCHUNK  (IN_DIM / KC)      // 8
#define APAD    36                 // row stride in floats (conflict-free: row*4+c distinct)

// ---------------- device scratch ----------------
__device__ int g_counts[KEXP];
__device__ int g_cursor[KEXP];
__device__ int g_perm[NTOK];
__device__ int g_tile_expert[MAX_TILES];
__device__ int g_tile_start[MAX_TILES];
__device__ int g_tile_len[MAX_TILES];
__device__ int g_num_tiles;
__device__ float g_W1t[KEXP * OUT_DIM * IN_DIM];   // [e][n][k], tf32-RN-rounded

// ---------------- helpers ----------------
__device__ __forceinline__ uint32_t smem_u32(const void* p) {
    uint32_t a;
    asm("{ .reg .u64 t; cvta.to.shared.u64 t, %1; cvt.u32.u64 %0, t; }" : "=r"(a) : "l"(p));
    return a;
}
__device__ __forceinline__ void cp_async16(uint32_t dst, const void* src) {
    asm volatile("cp.async.cg.shared.global [%0], [%1], 16;" :: "r"(dst), "l"(src) : "memory");
}
#define CP_COMMIT()  asm volatile("cp.async.commit_group;" ::: "memory")
#define CP_WAIT(n)   asm volatile("cp.async.wait_group %0;" :: "n"(n) : "memory")

__device__ __forceinline__ void mma_tf32(float& d0, float& d1, float& d2, float& d3,
                                         uint32_t a0, uint32_t a1, uint32_t a2, uint32_t a3,
                                         uint32_t b0, uint32_t b1) {
    asm volatile(
        "mma.sync.aligned.m16n8k8.row.col.f32.tf32.tf32.f32 "
        "{%0,%1,%2,%3}, {%4,%5,%6,%7}, {%8,%9}, {%0,%1,%2,%3};"
        : "+f"(d0), "+f"(d1), "+f"(d2), "+f"(d3)
        : "r"(a0), "r"(a1), "r"(a2), "r"(a3), "r"(b0), "r"(b1));
}

// ---------------- 1. zero counters ----------------
__global__ void zero_kernel() {
    int tid = threadIdx.x;
    if (tid < KEXP) g_counts[tid] = 0;
}

// ---------------- 2. histogram ----------------
__global__ void hist_kernel(const int* __restrict__ z) {
    __shared__ int sh[KEXP];
    int tid = threadIdx.x;
    if (tid < KEXP) sh[tid] = 0;
    __syncthreads();
    int i = blockIdx.x * blockDim.x + tid;
    atomicAdd(&sh[z[i]], 1);
    __syncthreads();
    if (tid < KEXP) atomicAdd(&g_counts[tid], sh[tid]);
}

// ---------------- 3. scan + tile table ----------------
__global__ void scan_kernel() {
    __shared__ int s_off[KEXP + 1];
    __shared__ int s_tp[KEXP + 1];
    int tid = threadIdx.x;
    if (tid == 0) {
        int off = 0, tp = 0;
        for (int e = 0; e < KEXP; e++) {
            s_off[e] = off; s_tp[e] = tp;
            g_cursor[e] = off;
            int c = g_counts[e];
            off += c;
            tp += (c + TILE_M - 1) / TILE_M;
        }
        s_off[KEXP] = off; s_tp[KEXP] = tp;
        g_num_tiles = tp;
    }
    __syncthreads();
    int total = s_tp[KEXP];
    for (int idx = tid; idx < total; idx += blockDim.x) {
        int e = 0;
        while (s_tp[e + 1] <= idx) e++;
        int t = idx - s_tp[e];
        g_tile_expert[idx] = e;
        g_tile_start[idx] = s_off[e] + t * TILE_M;
        int rem = g_counts[e] - t * TILE_M;
        g_tile_len[idx] = rem < TILE_M ? rem : TILE_M;
    }
}

// ---------------- 4. scatter ----------------
__global__ void scatter_kernel(const int* __restrict__ z) {
    __shared__ int sh_cnt[KEXP];
    __shared__ int sh_base[KEXP];
    int tid = threadIdx.x;
    if (tid < KEXP) sh_cnt[tid] = 0;
    __syncthreads();
    int i = blockIdx.x * blockDim.x + tid;
    int e = z[i];
    int lr = atomicAdd(&sh_cnt[e], 1);
    __syncthreads();
    if (tid < KEXP) {
        int c = sh_cnt[tid];
        sh_base[tid] = (c > 0) ? atomicAdd(&g_cursor[tid], c) : 0;
    }
    __syncthreads();
    g_perm[sh_base[e] + lr] = i;
}

// ---------------- 5. W1 transpose [e][k][n] -> [e][n][k], tf32-RN ----------------
__global__ void w1t_kernel(const float* __restrict__ W1) {
    __shared__ float t[32][33];
    int e  = blockIdx.y;
    int k0 = (blockIdx.x & 7) * 32;
    int n0 = (blockIdx.x >> 3) * 32;
    int tx = threadIdx.x, ty = threadIdx.y;
    const float* src = W1 + ((size_t)e * IN_DIM + k0) * OUT_DIM + n0;
#pragma unroll
    for (int d = 0; d < 32; d += 8)
        t[ty + d][tx] = src[(ty + d) * OUT_DIM + tx];
    __syncthreads();
    uint32_t* dst = (uint32_t*)(g_W1t + ((size_t)e * OUT_DIM + n0) * IN_DIM + k0);
#pragma unroll
    for (int d = 0; d < 32; d += 8) {
        uint32_t r;
        asm("cvt.rn.tf32.f32 %0, %1;" : "=r"(r) : "f"(t[tx][ty + d]));
        dst[(ty + d) * IN_DIM + tx] = r;
    }
}

// ---------------- 6. HMMA tf32 MLP ----------------
struct MlpSmem {
    float  As[2][TILE_M][APAD];     // x gather chunks   (36864 B)
    float  Bs[2][OUT_DIM][APAD];    // W1t chunks        (36864 B)
    int    tok[TILE_M];
    float  b1v[OUT_DIM];
    float2 w2v[OUT_DIM];
    float2 pp[TILE_M][2];           // per-half logit partials
};
#define DYN_SMEM ((int)sizeof(MlpSmem))

__global__ __launch_bounds__(256, 2)
void mlp_mma_kernel(const float* __restrict__ x,
                    const float* __restrict__ b1,
                    const float* __restrict__ W2,
                    const float* __restrict__ b2,
                    float* __restrict__ out)
{
    extern __shared__ char dyn[];
    MlpSmem* s = (MlpSmem*)dyn;

    int bid = blockIdx.x;
    if (bid >= g_num_tiles) return;
    int e     = g_tile_expert[bid];
    int start = g_tile_start[bid];
    int len   = g_tile_len[bid];

    int tid = threadIdx.x;
    int wid  = tid >> 5;
    int lane = tid & 31;
    int warp_m = wid >> 1;          // 0..3 -> 32 rows each
    int warp_n = wid & 1;           // 0..1 -> 64 cols each
    int r0 = lane >> 2;             // 0..7
    int cq = lane & 3;              // 0..3

    if (tid < TILE_M) {
        s->tok[tid] = g_perm[start + (tid < len ? tid : len - 1)];
        s->b1v[tid] = b1[e * OUT_DIM + tid];
        s->w2v[tid] = ((const float2*)(W2 + (size_t)e * OUT_DIM * 2))[tid];
    }
    __syncthreads();

    const float* W1te = g_W1t + (size_t)e * OUT_DIM * IN_DIM;

    // stage chunk c into buffer c&1
    auto stage = [&](int c) {
        int buf = c & 1;
        int k0 = c * KC;
#pragma unroll
        for (int j = 0; j < 4; j++) {
            int t = j * 256 + tid;          // 0..1023
            int m = t >> 3, q = t & 7;
            cp_async16(smem_u32(&s->As[buf][m][q * 4]),
                       x + (size_t)s->tok[m] * IN_DIM + k0 + q * 4);
            cp_async16(smem_u32(&s->Bs[buf][m][q * 4]),
                       W1te + (size_t)m * IN_DIM + k0 + q * 4);
        }
        CP_COMMIT();
    };

    float acc[2][8][4];
#pragma unroll
    for (int mt = 0; mt < 2; mt++)
#pragma unroll
        for (int nt = 0; nt < 8; nt++)
#pragma unroll
            for (int v = 0; v < 4; v++) acc[mt][nt][v] = 0.f;

    stage(0);

#pragma unroll
    for (int i = 0; i < NCHUNK; i++) {
        __syncthreads();                    // other buffer's previous chunk consumed
        if (i + 1 < NCHUNK) { stage(i + 1); CP_WAIT(1); }
        else                { CP_WAIT(0); }
        __syncthreads();

        int buf = i & 1;
        const float (*A)[APAD] = &s->As[buf][warp_m * 32];
        const float (*B)[APAD] = &s->Bs[buf][warp_n * 64];

#pragma unroll
        for (int ks = 0; ks < KC / 8; ks++) {
            int kb = ks * 8;
            uint32_t af[2][4];
#pragma unroll
            for (int mt = 0; mt < 2; mt++) {
                af[mt][0] = __float_as_uint(A[mt * 16 + r0    ][kb + cq    ]);
                af[mt][1] = __float_as_uint(A[mt * 16 + r0 + 8][kb + cq    ]);
                af[mt][2] = __float_as_uint(A[mt * 16 + r0    ][kb + cq + 4]);
                af[mt][3] = __float_as_uint(A[mt * 16 + r0 + 8][kb + cq + 4]);
            }
#pragma unroll
            for (int nt = 0; nt < 8; nt++) {
                uint32_t b0 = __float_as_uint(B[nt * 8 + r0][kb + cq    ]);
                uint32_t b1f = __float_as_uint(B[nt * 8 + r0][kb + cq + 4]);
#pragma unroll
                for (int mt = 0; mt < 2; mt++)
                    mma_tf32(acc[mt][nt][0], acc[mt][nt][1], acc[mt][nt][2], acc[mt][nt][3],
                             af[mt][0], af[mt][1], af[mt][2], af[mt][3], b0, b1f);
            }
        }
    }

    // epilogue: bias + relu + layer2 partials
    float p0[2][2], p1[2][2];
#pragma unroll
    for (int mt = 0; mt < 2; mt++)
#pragma unroll
        for (int h = 0; h < 2; h++) { p0[mt][h] = 0.f; p1[mt][h] = 0.f; }

#pragma unroll
    for (int nt = 0; nt < 8; nt++) {
        int c = warp_n * 64 + nt * 8 + cq * 2;
        float  ba = s->b1v[c], bb = s->b1v[c + 1];
        float2 wa = s->w2v[c], wb = s->w2v[c + 1];
#pragma unroll
        for (int mt = 0; mt < 2; mt++) {
            float h00 = fmaxf(acc[mt][nt][0] + ba, 0.f);
            float h01 = fmaxf(acc[mt][nt][1] + bb, 0.f);
            p0[mt][0] = fmaf(h00, wa.x, fmaf(h01, wb.x, p0[mt][0]));
            p1[mt][0] = fmaf(h00, wa.y, fmaf(h01, wb.y, p1[mt][0]));
            float h10 = fmaxf(acc[mt][nt][2] + ba, 0.f);
            float h11 = fmaxf(acc[mt][nt][3] + bb, 0.f);
            p0[mt][1] = fmaf(h10, wa.x, fmaf(h11, wb.x, p0[mt][1]));
            p1[mt][1] = fmaf(h10, wa.y, fmaf(h11, wb.y, p1[mt][1]));
        }
    }
    // reduce over the 4-lane quad (cq bits)
#pragma unroll
    for (int mt = 0; mt < 2; mt++)
#pragma unroll
        for (int h = 0; h < 2; h++) {
            p0[mt][h] += __shfl_xor_sync(0xFFFFFFFFu, p0[mt][h], 1);
            p1[mt][h] += __shfl_xor_sync(0xFFFFFFFFu, p1[mt][h], 1);
            p0[mt][h] += __shfl_xor_sync(0xFFFFFFFFu, p0[mt][h], 2);
            p1[mt][h] += __shfl_xor_sync(0xFFFFFFFFu, p1[mt][h], 2);
        }
    if (cq == 0) {
#pragma unroll
        for (int mt = 0; mt < 2; mt++)
#pragma unroll
            for (int h = 0; h < 2; h++) {
                int row = warp_m * 32 + mt * 16 + h * 8 + r0;
                s->pp[row][warp_n] = make_float2(p0[mt][h], p1[mt][h]);
            }
    }
    __syncthreads();

    if (tid < TILE_M && tid < len) {
        float2 a = s->pp[tid][0], b = s->pp[tid][1];
        float l0 = a.x + b.x + b2[e * 2 + 0];
        float l1 = a.y + b.y + b2[e * 2 + 1];
        float mx = fmaxf(l0, l1);
        float e0 = expf(l0 - mx);
        float e1 = expf(l1 - mx);
        float inv = 1.f / (e0 + e1);
        ((float2*)out)[s->tok[tid]] = make_float2(e0 * inv, e1 * inv);
    }
}

// ---------------- launch ----------------
extern "C" void kernel_launch(void* const* d_in, const int* in_sizes, int n_in,
                              void* d_out, int out_size) {
    const float* x  = (const float*)d_in[0];
    const int*   z  = (const int*)d_in[1];
    const float* W1 = (const float*)d_in[2];
    const float* b1 = (const float*)d_in[3];
    const float* W2 = (const float*)d_in[4];
    const float* b2 = (const float*)d_in[5];
    float* out = (float*)d_out;

    cudaFuncSetAttribute(mlp_mma_kernel, cudaFuncAttributeMaxDynamicSharedMemorySize, DYN_SMEM);

    zero_kernel<<<1, 32>>>();
    hist_kernel<<<NTOK / 256, 256>>>(z);
    scan_kernel<<<1, 256>>>();
    w1t_kernel<<<dim3(32, KEXP), dim3(32, 8)>>>(W1);
    scatter_kernel<<<NTOK / 256, 256>>>(z);
    mlp_mma_kernel<<<MAX_TILES, 256, DYN_SMEM>>>(x, b1, W2, b2, out);
}

// round 4
// speedup vs baseline: 3.7851x; 1.0663x over previous
#include <cuda_runtime.h>
#include <cuda_bf16.h>
#include <cstdint>
#include <math.h>

#define NTOK    131072
#define KEXP    16
#define IN_DIM  256
#define OUT_DIM 128
#define TILE_M  128
#define MAX_TILES (NTOK / TILE_M + KEXP - 1)

#define KC      32                 // k elements per chunk
#define NCHUNK  (IN_DIM / KC)      // 8
#define AW      20                 // word stride (16 data words + 4 pad) -> conflict-free

// ---------------- device scratch ----------------
__device__ int g_counts[KEXP];
__device__ int g_cursor[KEXP];
__device__ int g_perm[NTOK];
__device__ int g_tile_expert[MAX_TILES];
__device__ int g_tile_start[MAX_TILES];
__device__ int g_tile_len[MAX_TILES];
__device__ int g_num_tiles;
__device__ __nv_bfloat16 g_W1b[KEXP * OUT_DIM * IN_DIM];   // [e][n][k] bf16

// ---------------- helpers ----------------
__device__ __forceinline__ uint32_t smem_u32(const void* p) {
    uint32_t a;
    asm("{ .reg .u64 t; cvta.to.shared.u64 t, %1; cvt.u32.u64 %0, t; }" : "=r"(a) : "l"(p));
    return a;
}
__device__ __forceinline__ void cp_async16(uint32_t dst, const void* src) {
    asm volatile("cp.async.cg.shared.global [%0], [%1], 16;" :: "r"(dst), "l"(src) : "memory");
}
#define CP_COMMIT()  asm volatile("cp.async.commit_group;" ::: "memory")
#define CP_WAIT0()   asm volatile("cp.async.wait_group 0;" ::: "memory")

__device__ __forceinline__ uint32_t pack_bf16(float lo, float hi) {
    uint32_t r;
    asm("cvt.rn.bf16x2.f32 %0, %1, %2;" : "=r"(r) : "f"(hi), "f"(lo));
    return r;
}
__device__ __forceinline__ void mma_bf16(float& d0, float& d1, float& d2, float& d3,
                                         uint32_t a0, uint32_t a1, uint32_t a2, uint32_t a3,
                                         uint32_t b0, uint32_t b1) {
    asm volatile(
        "mma.sync.aligned.m16n8k16.row.col.f32.bf16.bf16.f32 "
        "{%0,%1,%2,%3}, {%4,%5,%6,%7}, {%8,%9}, {%0,%1,%2,%3};"
        : "+f"(d0), "+f"(d1), "+f"(d2), "+f"(d3)
        : "r"(a0), "r"(a1), "r"(a2), "r"(a3), "r"(b0), "r"(b1));
}

// ---------------- 1. histogram (4 tokens/thread) ----------------
__global__ void hist_kernel(const int* __restrict__ z) {
    __shared__ int sh[KEXP];
    int tid = threadIdx.x;
    if (tid < KEXP) sh[tid] = 0;
    __syncthreads();
    int i = blockIdx.x * blockDim.x + tid;       // grid*block*4 == NTOK
    int4 v = ((const int4*)z)[i];
    atomicAdd(&sh[v.x], 1);
    atomicAdd(&sh[v.y], 1);
    atomicAdd(&sh[v.z], 1);
    atomicAdd(&sh[v.w], 1);
    __syncthreads();
    if (tid < KEXP) atomicAdd(&g_counts[tid], sh[tid]);
}

// ---------------- 2. scan + tile table ----------------
__global__ void scan_kernel() {
    __shared__ int s_off[KEXP + 1];
    __shared__ int s_tp[KEXP + 1];
    int tid = threadIdx.x;
    if (tid == 0) {
        int off = 0, tp = 0;
        for (int e = 0; e < KEXP; e++) {
            s_off[e] = off; s_tp[e] = tp;
            g_cursor[e] = off;
            int c = g_counts[e];
            off += c;
            tp += (c + TILE_M - 1) / TILE_M;
        }
        s_off[KEXP] = off; s_tp[KEXP] = tp;
        g_num_tiles = tp;
    }
    __syncthreads();
    int total = s_tp[KEXP];
    for (int idx = tid; idx < total; idx += blockDim.x) {
        int e = 0;
        while (s_tp[e + 1] <= idx) e++;
        int t = idx - s_tp[e];
        g_tile_expert[idx] = e;
        g_tile_start[idx] = s_off[e] + t * TILE_M;
        int rem = g_counts[e] - t * TILE_M;
        g_tile_len[idx] = rem < TILE_M ? rem : TILE_M;
    }
}

// ---------------- 3. scatter (4 tokens/thread) + reset g_counts for next replay ----
__global__ void scatter_kernel(const int* __restrict__ z) {
    __shared__ int sh_cnt[KEXP];
    __shared__ int sh_base[KEXP];
    int tid = threadIdx.x;
    if (blockIdx.x == 0 && tid < KEXP) g_counts[tid] = 0;   // scan already consumed them
    if (tid < KEXP) sh_cnt[tid] = 0;
    __syncthreads();
    int i = blockIdx.x * blockDim.x + tid;
    int4 v = ((const int4*)z)[i];
    int r0 = atomicAdd(&sh_cnt[v.x], 1);
    int r1 = atomicAdd(&sh_cnt[v.y], 1);
    int r2 = atomicAdd(&sh_cnt[v.z], 1);
    int r3 = atomicAdd(&sh_cnt[v.w], 1);
    __syncthreads();
    if (tid < KEXP) {
        int c = sh_cnt[tid];
        sh_base[tid] = (c > 0) ? atomicAdd(&g_cursor[tid], c) : 0;
    }
    __syncthreads();
    g_perm[sh_base[v.x] + r0] = i * 4 + 0;
    g_perm[sh_base[v.y] + r1] = i * 4 + 1;
    g_perm[sh_base[v.z] + r2] = i * 4 + 2;
    g_perm[sh_base[v.w] + r3] = i * 4 + 3;
}

// ---------------- 4. W1 transpose [e][k][n] -> [e][n][k] bf16 ----------------
__global__ void w1t_kernel(const float* __restrict__ W1) {
    __shared__ float t[32][33];
    int e  = blockIdx.y;
    int k0 = (blockIdx.x & 7) * 32;
    int n0 = (blockIdx.x >> 3) * 32;
    int tx = threadIdx.x, ty = threadIdx.y;
    const float* src = W1 + ((size_t)e * IN_DIM + k0) * OUT_DIM + n0;
#pragma unroll
    for (int d = 0; d < 32; d += 8)
        t[ty + d][tx] = src[(ty + d) * OUT_DIM + tx];
    __syncthreads();
    __nv_bfloat16* dst = g_W1b + ((size_t)e * OUT_DIM + n0) * IN_DIM + k0;
#pragma unroll
    for (int d = 0; d < 32; d += 8)
        dst[(ty + d) * IN_DIM + tx] = __float2bfloat16_rn(t[tx][ty + d]);
}

// ---------------- 5. bf16 HMMA MLP ----------------
struct MlpSmem {
    uint32_t As[2][TILE_M][AW];     // x chunks, packed bf16x2 (k pairs) : 20480 B
    uint32_t Bs[2][OUT_DIM][AW];    // W1b chunks, packed bf16x2        : 20480 B
    int    tok[TILE_M];
    float  b1v[OUT_DIM];
    float2 w2v[OUT_DIM];
    float2 pp[TILE_M][2];
};
#define DYN_SMEM ((int)sizeof(MlpSmem))

__global__ __launch_bounds__(256, 2)
void mlp_mma_kernel(const float* __restrict__ x,
                    const float* __restrict__ b1,
                    const float* __restrict__ W2,
                    const float* __restrict__ b2,
                    float* __restrict__ out)
{
    extern __shared__ char dyn[];
    MlpSmem* s = (MlpSmem*)dyn;

    int bid = blockIdx.x;
    if (bid >= g_num_tiles) return;
    int e     = g_tile_expert[bid];
    int start = g_tile_start[bid];
    int len   = g_tile_len[bid];

    int tid = threadIdx.x;
    int wid  = tid >> 5;
    int lane = tid & 31;
    int warp_m = wid >> 1;          // 4 groups of 32 rows
    int warp_n = wid & 1;           // 2 groups of 64 cols
    int r0 = lane >> 2;             // 0..7
    int cq = lane & 3;              // 0..3

    if (tid < TILE_M) {
        s->tok[tid] = g_perm[start + (tid < len ? tid : len - 1)];
        s->b1v[tid] = b1[e * OUT_DIM + tid];
        s->w2v[tid] = ((const float2*)(W2 + (size_t)e * OUT_DIM * 2))[tid];
    }
    __syncthreads();

    const __nv_bfloat16* W1be = g_W1b + (size_t)e * OUT_DIM * IN_DIM;

    // ---- A staging: LDG fp32 -> pack bf16x2 -> STS. thread: row m = tid>>1, half h ----
    int am = tid >> 1;
    int ah = tid & 1;
    const float4* asrc_base = (const float4*)(x + (size_t)s->tok[am] * IN_DIM + ah * 16);

    float4 pf[4];
    auto ldgA = [&](int c) {
        const float4* p = asrc_base + c * (KC / 4);
#pragma unroll
        for (int j = 0; j < 4; j++) pf[j] = p[j];
    };
    auto stsA = [&](int c) {
        int buf = c & 1;
        uint32_t* d = &s->As[buf][am][ah * 8];
        uint4 w0, w1;
        w0.x = pack_bf16(pf[0].x, pf[0].y); w0.y = pack_bf16(pf[0].z, pf[0].w);
        w0.z = pack_bf16(pf[1].x, pf[1].y); w0.w = pack_bf16(pf[1].z, pf[1].w);
        w1.x = pack_bf16(pf[2].x, pf[2].y); w1.y = pack_bf16(pf[2].z, pf[2].w);
        w1.z = pack_bf16(pf[3].x, pf[3].y); w1.w = pack_bf16(pf[3].z, pf[3].w);
        *(uint4*)d       = w0;
        *(uint4*)(d + 4) = w1;
    };
    // ---- B staging via cp.async: 512 x 16B, thread handles 2 ----
    int bm = tid >> 1;              // row 0..127
    int bq = (tid & 1) * 2;         // q in {0,2}; each covers q and q+1
    auto cpB = [&](int c) {
        int buf = c & 1;
        const __nv_bfloat16* srcb = W1be + (size_t)bm * IN_DIM + c * KC;
        cp_async16(smem_u32(&s->Bs[buf][bm][bq * 4]),     srcb + bq * 8);
        cp_async16(smem_u32(&s->Bs[buf][bm][bq * 4 + 4]), srcb + bq * 8 + 8);
        CP_COMMIT();
    };

    float acc[2][8][4];
#pragma unroll
    for (int mt = 0; mt < 2; mt++)
#pragma unroll
        for (int nt = 0; nt < 8; nt++)
#pragma unroll
            for (int v = 0; v < 4; v++) acc[mt][nt][v] = 0.f;

    ldgA(0);
    cpB(0);

#pragma unroll
    for (int i = 0; i < NCHUNK; i++) {
        int buf = i & 1;
        stsA(i);
        if (i + 1 < NCHUNK) ldgA(i + 1);   // LDG latency hidden by MMAs below
        CP_WAIT0();                        // B_i arrived
        __syncthreads();                   // A STS visible; prev-chunk MMAs drained

        if (i + 1 < NCHUNK) cpB(i + 1);    // other buffer free (chunk i-1 consumed)

        int arow = warp_m * 32;
        int brow = warp_n * 64;
#pragma unroll
        for (int ks = 0; ks < 2; ks++) {
            int kb = ks * 8;
            uint32_t af[2][4];
#pragma unroll
            for (int mt = 0; mt < 2; mt++) {
                af[mt][0] = s->As[buf][arow + mt * 16 + r0    ][kb + cq    ];
                af[mt][1] = s->As[buf][arow + mt * 16 + r0 + 8][kb + cq    ];
                af[mt][2] = s->As[buf][arow + mt * 16 + r0    ][kb + cq + 4];
                af[mt][3] = s->As[buf][arow + mt * 16 + r0 + 8][kb + cq + 4];
            }
#pragma unroll
            for (int nt = 0; nt < 8; nt++) {
                uint32_t b0 = s->Bs[buf][brow + nt * 8 + r0][kb + cq    ];
                uint32_t b1f = s->Bs[buf][brow + nt * 8 + r0][kb + cq + 4];
#pragma unroll
                for (int mt = 0; mt < 2; mt++)
                    mma_bf16(acc[mt][nt][0], acc[mt][nt][1], acc[mt][nt][2], acc[mt][nt][3],
                             af[mt][0], af[mt][1], af[mt][2], af[mt][3], b0, b1f);
            }
        }
    }

    // epilogue: bias + relu + layer2 partials
    float p0[2][2], p1[2][2];
#pragma unroll
    for (int mt = 0; mt < 2; mt++)
#pragma unroll
        for (int h = 0; h < 2; h++) { p0[mt][h] = 0.f; p1[mt][h] = 0.f; }

#pragma unroll
    for (int nt = 0; nt < 8; nt++) {
        int c = warp_n * 64 + nt * 8 + cq * 2;
        float  ba = s->b1v[c], bb = s->b1v[c + 1];
        float2 wa = s->w2v[c], wb = s->w2v[c + 1];
#pragma unroll
        for (int mt = 0; mt < 2; mt++) {
            float h00 = fmaxf(acc[mt][nt][0] + ba, 0.f);
            float h01 = fmaxf(acc[mt][nt][1] + bb, 0.f);
            p0[mt][0] = fmaf(h00, wa.x, fmaf(h01, wb.x, p0[mt][0]));
            p1[mt][0] = fmaf(h00, wa.y, fmaf(h01, wb.y, p1[mt][0]));
            float h10 = fmaxf(acc[mt][nt][2] + ba, 0.f);
            float h11 = fmaxf(acc[mt][nt][3] + bb, 0.f);
            p0[mt][1] = fmaf(h10, wa.x, fmaf(h11, wb.x, p0[mt][1]));
            p1[mt][1] = fmaf(h10, wa.y, fmaf(h11, wb.y, p1[mt][1]));
        }
    }
#pragma unroll
    for (int mt = 0; mt < 2; mt++)
#pragma unroll
        for (int h = 0; h < 2; h++) {
            p0[mt][h] += __shfl_xor_sync(0xFFFFFFFFu, p0[mt][h], 1);
            p1[mt][h] += __shfl_xor_sync(0xFFFFFFFFu, p1[mt][h], 1);
            p0[mt][h] += __shfl_xor_sync(0xFFFFFFFFu, p0[mt][h], 2);
            p1[mt][h] += __shfl_xor_sync(0xFFFFFFFFu, p1[mt][h], 2);
        }
    if (cq == 0) {
#pragma unroll
        for (int mt = 0; mt < 2; mt++)
#pragma unroll
            for (int h = 0; h < 2; h++) {
                int row = warp_m * 32 + mt * 16 + h * 8 + r0;
                s->pp[row][warp_n] = make_float2(p0[mt][h], p1[mt][h]);
            }
    }
    __syncthreads();

    if (tid < TILE_M && tid < len) {
        float2 a = s->pp[tid][0], b = s->pp[tid][1];
        float l0 = a.x + b.x + b2[e * 2 + 0];
        float l1 = a.y + b.y + b2[e * 2 + 1];
        float mx = fmaxf(l0, l1);
        float e0 = expf(l0 - mx);
        float e1 = expf(l1 - mx);
        float inv = 1.f / (e0 + e1);
        ((float2*)out)[s->tok[tid]] = make_float2(e0 * inv, e1 * inv);
    }
}

// ---------------- launch ----------------
extern "C" void kernel_launch(void* const* d_in, const int* in_sizes, int n_in,
                              void* d_out, int out_size) {
    const float* x  = (const float*)d_in[0];
    const int*   z  = (const int*)d_in[1];
    const float* W1 = (const float*)d_in[2];
    const float* b1 = (const float*)d_in[3];
    const float* W2 = (const float*)d_in[4];
    const float* b2 = (const float*)d_in[5];
    float* out = (float*)d_out;

    cudaFuncSetAttribute(mlp_mma_kernel, cudaFuncAttributeMaxDynamicSharedMemorySize, DYN_SMEM);

    hist_kernel<<<NTOK / 1024, 256>>>(z);
    scan_kernel<<<1, 256>>>();
    w1t_kernel<<<dim3(32, KEXP), dim3(32, 8)>>>(W1);
    scatter_kernel<<<NTOK / 1024, 256>>>(z);
    mlp_mma_kernel<<<MAX_TILES, 256, DYN_SMEM>>>(x, b1, W2, b2, out);
}